// round 12
// baseline (speedup 1.0000x reference)
#include <cuda_runtime.h>
#include <math.h>
#include <float.h>

#define NPTS 8192
#define BATCH 2
#define VOXD 64
#define VOXH 128
#define VOXW 128
#define VOX (VOXD*VOXH*VOXW)
#define DPIX (512*512)

// grid: exactly 148 blocks x 256 threads, one block per SM.
#define CHAM_BLKS 128      // 2 dir * 2 batch * 32 chunks of 256 A-points
#define CL_BLKS   16       // bids 128..143
#define DP_BLKS   4        // bids 144..147
#define TOT_BLKS  (CHAM_BLKS + CL_BLKS + DP_BLKS)   // 148

#define QTILE 256          // q points staged in smem per chunk

// partials
__device__ float g_cham[CHAM_BLKS];        // per-block sum of per-A min dists
__device__ float g_cl[BATCH * CL_BLKS * 3];// [b][blk]{inter,psum,gsum}
__device__ float g_dp[BATCH * DP_BLKS * 6];// [b][blk]{g,g2,gx,gy,l1,mask}
__device__ unsigned int g_cnt = 0;         // completion counter (self-resetting)

// ---------------- helpers ----------------
__device__ __forceinline__ unsigned long long pack2(float a, float b) {
    unsigned long long r;
    asm("mov.b64 %0, {%1, %2};" : "=l"(r) : "f"(a), "f"(b));
    return r;
}
__device__ __forceinline__ unsigned long long fma2(unsigned long long a,
                                                   unsigned long long b,
                                                   unsigned long long c) {
    unsigned long long d;
    asm("fma.rn.f32x2 %0, %1, %2, %3;" : "=l"(d) : "l"(a), "l"(b), "l"(c));
    return d;
}
__device__ __forceinline__ float lo2(unsigned long long v) {
    return __uint_as_float((unsigned)v);
}
__device__ __forceinline__ float hi2(unsigned long long v) {
    return __uint_as_float((unsigned)(v >> 32));
}
__device__ __forceinline__ float warp_sum(float v) {
#pragma unroll
    for (int o = 16; o > 0; o >>= 1) v += __shfl_xor_sync(0xffffffffu, v, o);
    return v;
}
__device__ __forceinline__ float min3f(float a, float b, float c) {
    return fminf(a, fminf(b, c));
}

// ===========================================================================
// Mega kernel: 1 block per SM, static role split, in-kernel finalize.
// ===========================================================================
__global__ void __launch_bounds__(256) mega_kernel(const float* __restrict__ pc,
                                                   const float* __restrict__ pv,
                                                   const float* __restrict__ pd,
                                                   const float* __restrict__ gp,
                                                   const float* __restrict__ gv,
                                                   const float* __restrict__ gd,
                                                   const float* __restrict__ dm,
                                                   const int* __restrict__ iter,
                                                   float* __restrict__ out) {
    // chamfer q tile: 128 pairs, packed (qx0,qx1,qy0,qy1) / (qz0,qz1,s0,s1)
    __shared__ __align__(16) float smA[QTILE * 2];
    __shared__ __align__(16) float smB[QTILE * 2];
    __shared__ float sred[16];
    __shared__ unsigned int sflag;

    const int bid = blockIdx.x;
    const int tid = threadIdx.x;
    const int lane = tid & 31;
    const int wid = tid >> 5;

    if (bid < CHAM_BLKS) {
        // ---------------- chamfer ----------------
        // d = |p|^2 + |q|^2 - 2 p.q = p2 + 2*(s - p.q), s = |q|^2/2
        // Each thread owns ONE A point; all lanes broadcast-read the q stream.
        const int dir = bid >> 6;
        const int b = (bid >> 5) & 1;
        const int chunk = bid & 31;
        const float* A  = (dir == 0 ? pc : gp) + (size_t)b * NPTS * 3;
        const float* Bp = (dir == 0 ? gp : pc) + (size_t)b * NPTS * 3;

        const int i = chunk * 256 + tid;
        const float ax = A[i * 3 + 0], ay = A[i * 3 + 1], az = A[i * 3 + 2];
        const float p2 = fmaf(ax, ax, fmaf(ay, ay, az * az));
        const unsigned long long nx = pack2(-ax, -ax);
        const unsigned long long ny = pack2(-ay, -ay);
        const unsigned long long nz = pack2(-az, -az);

        float bl = FLT_MAX, bh = FLT_MAX;
        const int pair = tid >> 1;
        const int half = tid & 1;

#pragma unroll 1
        for (int t0 = 0; t0 < NPTS; t0 += QTILE) {
            const int j = t0 + tid;
            const float qx = Bp[j * 3 + 0];
            const float qy = Bp[j * 3 + 1];
            const float qz = Bp[j * 3 + 2];
            const float s = 0.5f * fmaf(qx, qx, fmaf(qy, qy, qz * qz));
            __syncthreads();
            smA[pair * 4 + half] = qx;
            smA[pair * 4 + 2 + half] = qy;
            smB[pair * 4 + half] = qz;
            smB[pair * 4 + 2 + half] = s;
            __syncthreads();

            const ulonglong2* vA = (const ulonglong2*)smA;
            const ulonglong2* vB = (const ulonglong2*)smB;
#pragma unroll 8
            for (int p = 0; p < QTILE / 2; p++) {
                const ulonglong2 a = vA[p];   // (qx0,qx1)(qy0,qy1)  broadcast
                const ulonglong2 c = vB[p];   // (qz0,qz1)(s0,s1)    broadcast
                unsigned long long t = fma2(nx, a.x, c.y);
                t = fma2(ny, a.y, t);
                t = fma2(nz, c.x, t);
                bl = fminf(bl, lo2(t));
                bh = fminf(bh, hi2(t));
            }
        }

        const float d = fmaf(2.f, fminf(bl, bh), p2);
        float v = warp_sum(d);
        if (lane == 0) sred[wid] = v;
        __syncthreads();
        if (tid == 0) {
            float s = 0.f;
#pragma unroll
            for (int w = 0; w < 8; w++) s += sred[w];
            g_cham[bid] = s;
        }
    } else if (bid < CHAM_BLKS + CL_BLKS) {
        // ---------------- clDice (16 blocks) ----------------
        // erode(sigmoid(x)) == sigmoid(erode(x)); float4 along W; rolling d.
        // Thread T handles col-group cg = T for BOTH batches.
        const int T = (bid - CHAM_BLKS) * 256 + tid;   // 0..4095
        const int h = T >> 5;
        const int w0 = (T & 31) * 4;

        const int rm = (h > 0) ? h - 1 : 0;
        const int rp = (h < VOXH - 1) ? h + 1 : h;
        int rowoff[3];
        rowoff[0] = rm * VOXW + w0;
        rowoff[1] = h * VOXW + w0;
        rowoff[2] = rp * VOXW + w0;
        const bool hasL = (w0 > 0);
        const bool hasR = (w0 < VOXW - 4);

        auto inplane = [&](const float* __restrict__ V, int d) -> float4 {
            const int base = d << 14;
            float4 m = make_float4(FLT_MAX, FLT_MAX, FLT_MAX, FLT_MAX);
#pragma unroll
            for (int r = 0; r < 3; r++) {
                const float4 c4 = *(const float4*)(V + base + rowoff[r]);
                const float L = hasL ? __ldg(V + base + rowoff[r] - 1) : c4.x;
                const float R = hasR ? __ldg(V + base + rowoff[r] + 4) : c4.w;
                m.x = fminf(m.x, min3f(L, c4.x, c4.y));
                m.y = fminf(m.y, min3f(c4.x, c4.y, c4.z));
                m.z = fminf(m.z, min3f(c4.y, c4.z, c4.w));
                m.w = fminf(m.w, min3f(c4.z, c4.w, R));
            }
            return m;
        };

        float acc[BATCH][3];
#pragma unroll
        for (int b = 0; b < BATCH; b++) {
            const float* P = pv + (size_t)b * VOX;
            const float* G = gv + (size_t)b * VOX;

            float4 pPrev = inplane(P, 0);
            float4 gPrev = inplane(G, 0);
            float4 pCur = pPrev, gCur = gPrev;

            float si = 0.f, sp = 0.f, sg = 0.f;
#pragma unroll 2
            for (int d = 0; d < VOXD; d++) {
                float4 pNext, gNext;
                if (d < VOXD - 1) {
                    pNext = inplane(P, d + 1);
                    gNext = inplane(G, d + 1);
                } else {
                    pNext = pCur;
                    gNext = gCur;
                }
                const float pox = min3f(pPrev.x, pCur.x, pNext.x);
                const float poy = min3f(pPrev.y, pCur.y, pNext.y);
                const float poz = min3f(pPrev.z, pCur.z, pNext.z);
                const float pow_ = min3f(pPrev.w, pCur.w, pNext.w);
                const float gox = min3f(gPrev.x, gCur.x, gNext.x);
                const float goy = min3f(gPrev.y, gCur.y, gNext.y);
                const float goz = min3f(gPrev.z, gCur.z, gNext.z);
                const float gow = min3f(gPrev.w, gCur.w, gNext.w);

                const float sx = __fdividef(1.f, 1.f + __expf(-pox));
                const float sy = __fdividef(1.f, 1.f + __expf(-poy));
                const float sz = __fdividef(1.f, 1.f + __expf(-poz));
                const float sw = __fdividef(1.f, 1.f + __expf(-pow_));

                si = fmaf(sx, gox, fmaf(sy, goy, fmaf(sz, goz, fmaf(sw, gow, si))));
                sp += (sx + sy) + (sz + sw);
                sg += (gox + goy) + (goz + gow);

                pPrev = pCur; gPrev = gCur;
                pCur = pNext; gCur = gNext;
            }
            acc[b][0] = si; acc[b][1] = sp; acc[b][2] = sg;
        }

        __shared__ float sr6[6][8];
#pragma unroll
        for (int b = 0; b < BATCH; b++)
#pragma unroll
            for (int q = 0; q < 3; q++) {
                const float v = warp_sum(acc[b][q]);
                if (lane == 0) sr6[b * 3 + q][wid] = v;
            }
        __syncthreads();
        if (tid < 6) {
            float a = 0.f;
#pragma unroll
            for (int q = 0; q < 8; q++) a += sr6[tid][q];
            const int b = tid / 3, c = tid % 3;
            const int blk = bid - CHAM_BLKS;
            g_cl[(b * CL_BLKS + blk) * 3 + c] = a;
        }
    } else {
        // ---------------- depth (4 blocks) ----------------
        const int T = (bid - CHAM_BLKS - CL_BLKS) * 256 + tid;  // 0..1023
        float accd[BATCH][6];
#pragma unroll
        for (int b = 0; b < BATCH; b++) {
            const float* P = pd + (size_t)b * DPIX;
            const float* G = gd + (size_t)b * DPIX;
            const float* M = dm + (size_t)b * DPIX;
            float s0 = 0.f, s1 = 0.f, s2 = 0.f, s3 = 0.f, s4 = 0.f, s5 = 0.f;
#pragma unroll 4
            for (int k = 0; k < 256; k++) {
                const int idx = k * 1024 + T;
                const int hh = idx >> 9;
                const int ww = idx & 511;
                const float p = P[idx];
                const float g = G[idx];
                const float lg = __logf(p + 0.1f) - __logf(g + 0.1f);
                s0 += lg;
                s1 = fmaf(lg, lg, s1);
                if (hh < 511) s2 += fabsf(fabsf(p - P[idx + 512]) - fabsf(g - G[idx + 512]));
                if (ww < 511) s3 += fabsf(fabsf(p - P[idx + 1]) - fabsf(g - G[idx + 1]));
                const float m = M[idx];
                s4 = fmaf(fabsf(p - g), m, s4);
                s5 += m;
            }
            accd[b][0] = s0; accd[b][1] = s1; accd[b][2] = s2;
            accd[b][3] = s3; accd[b][4] = s4; accd[b][5] = s5;
        }

        __shared__ float sr12[12][8];
#pragma unroll
        for (int b = 0; b < BATCH; b++)
#pragma unroll
            for (int q = 0; q < 6; q++) {
                const float v = warp_sum(accd[b][q]);
                if (lane == 0) sr12[b * 6 + q][wid] = v;
            }
        __syncthreads();
        if (tid < 12) {
            float a = 0.f;
#pragma unroll
            for (int q = 0; q < 8; q++) a += sr12[tid][q];
            const int b = tid / 6, c = tid % 6;
            const int blk = bid - CHAM_BLKS - CL_BLKS;
            g_dp[(b * DP_BLKS + blk) * 6 + c] = a;
        }
    }

    // ================= last-block finalize =================
    __threadfence();
    if (tid == 0) sflag = atomicAdd(&g_cnt, 1u);
    __syncthreads();
    if (sflag != TOT_BLKS - 1) return;
    if (tid == 0) g_cnt = 0;   // reset for next graph replay
    __threadfence();

    __shared__ float sq[7];
    __shared__ float sqd[6][2];

    if (wid == 0) {
        float v = 0.f;
#pragma unroll
        for (int i = lane; i < CHAM_BLKS; i += 32) v += g_cham[i];
        v = warp_sum(v);
        if (lane == 0) sq[0] = v;
    } else if (wid < 7) {
        const int idx = wid - 1;
        const int b = idx / 3, c = idx % 3;
        float v = (lane < CL_BLKS) ? g_cl[(b * CL_BLKS + lane) * 3 + c] : 0.f;
        v = warp_sum(v);
        if (lane == 0) sq[wid] = v;
    } else if (wid == 7) {
        if (lane < 12) {
            const int b = lane / 6, c = lane % 6;
            float a = 0.f;
#pragma unroll
            for (int k = 0; k < DP_BLKS; k++) a += g_dp[(b * DP_BLKS + k) * 6 + c];
            sqd[c][b] = a;
        }
    }
    __syncthreads();

    if (tid == 0) {
        const float chamfer = sq[0] / (float)(BATCH * NPTS);

        float dice_acc = 0.f;
#pragma unroll
        for (int b = 0; b < BATCH; b++) {
            const float inter = sq[1 + b * 3 + 0];
            const float psum = sq[1 + b * 3 + 1];
            const float gsum = sq[1 + b * 3 + 2];
            dice_acc += (2.f * inter + 1e-5f) / (psum + gsum + 1e-5f);
        }
        const float cldice = 1.f - dice_acc / (float)BATCH;

        float var_acc = 0.f, m2_acc = 0.f;
#pragma unroll
        for (int b = 0; b < BATCH; b++) {
            const float mean = sqd[0][b] / (float)DPIX;
            const float var = sqd[1][b] / (float)DPIX - mean * mean;
            var_acc += var;
            m2_acc += mean * mean;
        }
        const float silog = 10.f * (var_acc / (float)BATCH) + 10.f * (m2_acc / (float)BATCH);

        const float gx = sqd[2][0] + sqd[2][1];
        const float gy = sqd[3][0] + sqd[3][1];
        const float grad_l1 = gx / (float)(BATCH * 511 * 512) + gy / (float)(BATCH * 512 * 511);

        const float mask_l1 = (sqd[4][0] + sqd[4][1]) / (sqd[5][0] + sqd[5][1] + 1e-8f);

        const float dloss = silog + grad_l1 + mask_l1;

        int it = iter[0];
        if (it < 1) it = 1;
        const float gamma1 = 2.f * logf((float)it / 20000.f);

        out[0] = gamma1 * chamfer + 0.5f * cldice + 0.01f * dloss;
    }
}

extern "C" void kernel_launch(void* const* d_in, const int* in_sizes, int n_in,
                              void* d_out, int out_size) {
    const float* pc = (const float*)d_in[0];   // pred_centers [2,8192,3]
    const float* pv = (const float*)d_in[1];   // pred_volume  [2,1,64,128,128]
    const float* pd = (const float*)d_in[2];   // pred_depth   [2,512,512]
    const float* gp = (const float*)d_in[3];   // gt_points    [2,8192,3]
    const float* gv = (const float*)d_in[4];   // gt_volume    [2,1,64,128,128]
    const float* gd = (const float*)d_in[5];   // gt_depth     [2,512,512]
    const float* dm = (const float*)d_in[6];   // depth_mask   [2,512,512]
    const int* it   = (const int*)d_in[7];     // iteration (scalar)

    mega_kernel<<<TOT_BLKS, 256>>>(pc, pv, pd, gp, gv, gd, dm, it, (float*)d_out);
}

// round 13
// speedup vs baseline: 1.6153x; 1.6153x over previous
#include <cuda_runtime.h>
#include <math.h>
#include <float.h>

#define NPTS 8192
#define BATCH 2
#define VOXD 64
#define VOXH 128
#define VOXW 128
#define VOX (VOXD*VOXH*VOXW)
#define DPIX (512*512)

// grid: exactly 148 blocks x 512 threads, one per SM.
#define CHAM_BLKS 128   // dir(2) x b(2) x ablk(8) x qq(4)
#define CL_BLKS   16    // bids 128..143
#define DP_BLKS   4     // bids 144..147
#define TOT_BLKS  (CHAM_BLKS + CL_BLKS + DP_BLKS)   // 148
#define TPB 512

#define QTILE 512       // q staged per tile (4 tiles per 2048-q quarter)

// partials
__device__ float g_minq[4 * 4 * NPTS];        // [qq][dir*2+b][8192] per-A d partial
__device__ float g_cl[CL_BLKS * 3];           // per cl-block {inter,psum,gsum}
__device__ float g_dp[BATCH * DP_BLKS * 6];   // per dp-block x batch {g,g2,gx,gy,l1,mask}
__device__ unsigned int g_cnt = 0;            // completion counter (self-resetting)

// ---------------- helpers ----------------
__device__ __forceinline__ unsigned long long pack2(float a, float b) {
    unsigned long long r;
    asm("mov.b64 %0, {%1, %2};" : "=l"(r) : "f"(a), "f"(b));
    return r;
}
__device__ __forceinline__ unsigned long long fma2(unsigned long long a,
                                                   unsigned long long b,
                                                   unsigned long long c) {
    unsigned long long d;
    asm("fma.rn.f32x2 %0, %1, %2, %3;" : "=l"(d) : "l"(a), "l"(b), "l"(c));
    return d;
}
__device__ __forceinline__ float lo2(unsigned long long v) {
    return __uint_as_float((unsigned)v);
}
__device__ __forceinline__ float hi2(unsigned long long v) {
    return __uint_as_float((unsigned)(v >> 32));
}
__device__ __forceinline__ float warp_sum(float v) {
#pragma unroll
    for (int o = 16; o > 0; o >>= 1) v += __shfl_xor_sync(0xffffffffu, v, o);
    return v;
}
__device__ __forceinline__ float min3f(float a, float b, float c) {
    return fminf(a, fminf(b, c));
}

// ===========================================================================
// Mega kernel: 148 blocks x 512 threads, static roles, in-kernel finalize.
// ===========================================================================
__global__ void __launch_bounds__(TPB) mega_kernel(const float* __restrict__ pc,
                                                   const float* __restrict__ pv,
                                                   const float* __restrict__ pd,
                                                   const float* __restrict__ gp,
                                                   const float* __restrict__ gv,
                                                   const float* __restrict__ gd,
                                                   const float* __restrict__ dm,
                                                   const int* __restrict__ iter,
                                                   float* __restrict__ out) {
    // q tile: 256 pairs packed (qx0,qx1,qy0,qy1) / (qz0,qz1,s0,s1)
    __shared__ __align__(16) float smA[QTILE * 2];
    __shared__ __align__(16) float smB[QTILE * 2];
    __shared__ float sred[16];
    __shared__ float sqcl[6];
    __shared__ float sqdp[12];
    __shared__ float sct[1];
    __shared__ unsigned int sflag;

    const int bid = blockIdx.x;
    const int tid = threadIdx.x;
    const int lane = tid & 31;
    const int wid = tid >> 5;

    if (bid < CHAM_BLKS) {
        // ---------------- chamfer ----------------
        // d = |p|^2 + |q|^2 - 2 p.q = p2 + 2*(s - p.q), s = |q|^2/2
        // Thread owns 2 A points; all lanes broadcast-read the q stream.
        const int qq = bid & 3;
        const int ablk = (bid >> 2) & 7;
        const int db = bid >> 5;               // dir*2 + b
        const int dir = db >> 1;
        const float* A  = (dir == 0 ? pc : gp) + (size_t)(db & 1) * NPTS * 3;
        const float* Bp = (dir == 0 ? gp : pc) + (size_t)(db & 1) * NPTS * 3;

        const int a0 = ablk * 1024 + tid;
        const int a1 = a0 + TPB;
        const float ax0 = A[a0 * 3 + 0], ay0 = A[a0 * 3 + 1], az0 = A[a0 * 3 + 2];
        const float ax1 = A[a1 * 3 + 0], ay1 = A[a1 * 3 + 1], az1 = A[a1 * 3 + 2];
        const float p2_0 = fmaf(ax0, ax0, fmaf(ay0, ay0, az0 * az0));
        const float p2_1 = fmaf(ax1, ax1, fmaf(ay1, ay1, az1 * az1));

        const unsigned long long nx0 = pack2(-ax0, -ax0);
        const unsigned long long ny0 = pack2(-ay0, -ay0);
        const unsigned long long nz0 = pack2(-az0, -az0);
        const unsigned long long nx1 = pack2(-ax1, -ax1);
        const unsigned long long ny1 = pack2(-ay1, -ay1);
        const unsigned long long nz1 = pack2(-az1, -az1);

        float bl0 = FLT_MAX, bh0 = FLT_MAX, bl1 = FLT_MAX, bh1 = FLT_MAX;

        const int pair = tid >> 1;
        const int half = tid & 1;
        const int qbase = qq * 2048;

#pragma unroll 1
        for (int t0 = 0; t0 < 2048; t0 += QTILE) {
            const int j = qbase + t0 + tid;
            const float qx = Bp[j * 3 + 0];
            const float qy = Bp[j * 3 + 1];
            const float qz = Bp[j * 3 + 2];
            const float s = 0.5f * fmaf(qx, qx, fmaf(qy, qy, qz * qz));
            __syncthreads();
            smA[pair * 4 + half] = qx;
            smA[pair * 4 + 2 + half] = qy;
            smB[pair * 4 + half] = qz;
            smB[pair * 4 + 2 + half] = s;
            __syncthreads();

            const ulonglong2* vA = (const ulonglong2*)smA;
            const ulonglong2* vB = (const ulonglong2*)smB;
#pragma unroll 8
            for (int p = 0; p < QTILE / 2; p++) {
                const ulonglong2 a = vA[p];   // (qx0,qx1)(qy0,qy1)  broadcast
                const ulonglong2 c = vB[p];   // (qz0,qz1)(s0,s1)    broadcast
                unsigned long long t0r = fma2(nx0, a.x, c.y);
                t0r = fma2(ny0, a.y, t0r);
                t0r = fma2(nz0, c.x, t0r);
                unsigned long long t1r = fma2(nx1, a.x, c.y);
                t1r = fma2(ny1, a.y, t1r);
                t1r = fma2(nz1, c.x, t1r);
                bl0 = fminf(bl0, lo2(t0r));
                bh0 = fminf(bh0, hi2(t0r));
                bl1 = fminf(bl1, lo2(t1r));
                bh1 = fminf(bh1, hi2(t1r));
            }
        }

        // per-quarter partial distance (min over quarters is taken in finalize;
        // fmaf(2,m,p2) is monotone in m so min commutes exactly)
        const float d0 = fmaf(2.f, fminf(bl0, bh0), p2_0);
        const float d1 = fmaf(2.f, fminf(bl1, bh1), p2_1);
        g_minq[(qq * 4 + db) * NPTS + ablk * 1024 + tid] = d0;
        g_minq[(qq * 4 + db) * NPTS + ablk * 1024 + TPB + tid] = d1;
    } else if (bid < CHAM_BLKS + CL_BLKS) {
        // ---------------- clDice (16 blocks, one batch per block) ----------------
        // erode(sigmoid(x)) == sigmoid(erode(x)); float4 along W; rolling d.
        const int blk = bid - CHAM_BLKS;
        const int T = blk * TPB + tid;         // 0..8191
        const int b = T >> 12;                 // constant within a block
        const int cg = T & 4095;
        const int h = cg >> 5;
        const int w0 = (cg & 31) * 4;

        const float* P = pv + (size_t)b * VOX;
        const float* G = gv + (size_t)b * VOX;

        const int rm = (h > 0) ? h - 1 : 0;
        const int rp = (h < VOXH - 1) ? h + 1 : h;
        int rowoff[3];
        rowoff[0] = rm * VOXW + w0;
        rowoff[1] = h * VOXW + w0;
        rowoff[2] = rp * VOXW + w0;
        const bool hasL = (w0 > 0);
        const bool hasR = (w0 < VOXW - 4);

        auto inplane = [&](const float* __restrict__ V, int d) -> float4 {
            const int base = d << 14;
            float4 m = make_float4(FLT_MAX, FLT_MAX, FLT_MAX, FLT_MAX);
#pragma unroll
            for (int r = 0; r < 3; r++) {
                const float4 c4 = *(const float4*)(V + base + rowoff[r]);
                const float L = hasL ? __ldg(V + base + rowoff[r] - 1) : c4.x;
                const float R = hasR ? __ldg(V + base + rowoff[r] + 4) : c4.w;
                m.x = fminf(m.x, min3f(L, c4.x, c4.y));
                m.y = fminf(m.y, min3f(c4.x, c4.y, c4.z));
                m.z = fminf(m.z, min3f(c4.y, c4.z, c4.w));
                m.w = fminf(m.w, min3f(c4.z, c4.w, R));
            }
            return m;
        };

        float4 pPrev = inplane(P, 0);
        float4 gPrev = inplane(G, 0);
        float4 pCur = pPrev, gCur = gPrev;

        float si = 0.f, sp = 0.f, sg = 0.f;
#pragma unroll 2
        for (int d = 0; d < VOXD; d++) {
            float4 pNext, gNext;
            if (d < VOXD - 1) {
                pNext = inplane(P, d + 1);
                gNext = inplane(G, d + 1);
            } else {
                pNext = pCur;
                gNext = gCur;
            }
            const float pox = min3f(pPrev.x, pCur.x, pNext.x);
            const float poy = min3f(pPrev.y, pCur.y, pNext.y);
            const float poz = min3f(pPrev.z, pCur.z, pNext.z);
            const float pow_ = min3f(pPrev.w, pCur.w, pNext.w);
            const float gox = min3f(gPrev.x, gCur.x, gNext.x);
            const float goy = min3f(gPrev.y, gCur.y, gNext.y);
            const float goz = min3f(gPrev.z, gCur.z, gNext.z);
            const float gow = min3f(gPrev.w, gCur.w, gNext.w);

            const float sx = __fdividef(1.f, 1.f + __expf(-pox));
            const float sy = __fdividef(1.f, 1.f + __expf(-poy));
            const float sz = __fdividef(1.f, 1.f + __expf(-poz));
            const float sw = __fdividef(1.f, 1.f + __expf(-pow_));

            si = fmaf(sx, gox, fmaf(sy, goy, fmaf(sz, goz, fmaf(sw, gow, si))));
            sp += (sx + sy) + (sz + sw);
            sg += (gox + goy) + (goz + gow);

            pPrev = pCur; gPrev = gCur;
            pCur = pNext; gCur = gNext;
        }

        __shared__ float sr3[3][16];
        const float v0 = warp_sum(si), v1 = warp_sum(sp), v2 = warp_sum(sg);
        if (lane == 0) { sr3[0][wid] = v0; sr3[1][wid] = v1; sr3[2][wid] = v2; }
        __syncthreads();
        if (tid < 3) {
            float a = 0.f;
#pragma unroll
            for (int q = 0; q < 16; q++) a += sr3[tid][q];
            g_cl[blk * 3 + tid] = a;
        }
    } else {
        // ---------------- depth (4 blocks, both batches) ----------------
        const int blkrel = bid - CHAM_BLKS - CL_BLKS;
        const int T = blkrel * TPB + tid;       // 0..2047
        float accd[BATCH][6];
#pragma unroll
        for (int b = 0; b < BATCH; b++) {
            const float* P = pd + (size_t)b * DPIX;
            const float* G = gd + (size_t)b * DPIX;
            const float* M = dm + (size_t)b * DPIX;
            float s0 = 0.f, s1 = 0.f, s2 = 0.f, s3 = 0.f, s4 = 0.f, s5 = 0.f;
#pragma unroll 4
            for (int k = 0; k < 128; k++) {
                const int idx = k * 2048 + T;
                const int hh = idx >> 9;
                const int ww = idx & 511;
                const float p = P[idx];
                const float g = G[idx];
                const float lg = __logf(p + 0.1f) - __logf(g + 0.1f);
                s0 += lg;
                s1 = fmaf(lg, lg, s1);
                if (hh < 511) s2 += fabsf(fabsf(p - P[idx + 512]) - fabsf(g - G[idx + 512]));
                if (ww < 511) s3 += fabsf(fabsf(p - P[idx + 1]) - fabsf(g - G[idx + 1]));
                const float m = M[idx];
                s4 = fmaf(fabsf(p - g), m, s4);
                s5 += m;
            }
            accd[b][0] = s0; accd[b][1] = s1; accd[b][2] = s2;
            accd[b][3] = s3; accd[b][4] = s4; accd[b][5] = s5;
        }

        __shared__ float sr12[12][16];
#pragma unroll
        for (int b = 0; b < BATCH; b++)
#pragma unroll
            for (int q = 0; q < 6; q++) {
                const float v = warp_sum(accd[b][q]);
                if (lane == 0) sr12[b * 6 + q][wid] = v;
            }
        __syncthreads();
        if (tid < 12) {
            float a = 0.f;
#pragma unroll
            for (int q = 0; q < 16; q++) a += sr12[tid][q];
            const int b = tid / 6, c = tid % 6;
            g_dp[(b * DP_BLKS + blkrel) * 6 + c] = a;
        }
    }

    // ================= last-block finalize =================
    __threadfence();
    if (tid == 0) sflag = atomicAdd(&g_cnt, 1u);
    __syncthreads();
    if (sflag != TOT_BLKS - 1) return;
    if (tid == 0) g_cnt = 0;   // reset for next graph replay
    __threadfence();

    // chamfer: min over 4 quarters, then sum (all 512 threads)
    {
        float s = 0.f;
#pragma unroll 4
        for (int i = tid; i < 4 * NPTS; i += TPB) {
            const float m = fminf(fminf(g_minq[i], g_minq[4 * NPTS + i]),
                                  fminf(g_minq[8 * NPTS + i], g_minq[12 * NPTS + i]));
            s += m;
        }
        s = warp_sum(s);
        if (lane == 0) sred[wid] = s;
    }
    if (tid < 6) {
        const int b = tid / 3, c = tid % 3;
        float a = 0.f;
#pragma unroll
        for (int k = 0; k < 8; k++) a += g_cl[(b * 8 + k) * 3 + c];
        sqcl[tid] = a;
    }
    if (tid >= 32 && tid < 44) {
        const int j = tid - 32;
        const int b = j / 6, c = j % 6;
        float a = 0.f;
#pragma unroll
        for (int k = 0; k < DP_BLKS; k++) a += g_dp[(b * DP_BLKS + k) * 6 + c];
        sqdp[j] = a;
    }
    __syncthreads();
    if (tid == 0) {
        float s = 0.f;
#pragma unroll
        for (int w = 0; w < 16; w++) s += sred[w];
        sct[0] = s;
    }
    __syncthreads();

    if (tid == 0) {
        const float chamfer = sct[0] / (float)(BATCH * NPTS);

        float dice_acc = 0.f;
#pragma unroll
        for (int b = 0; b < BATCH; b++) {
            const float inter = sqcl[b * 3 + 0];
            const float psum = sqcl[b * 3 + 1];
            const float gsum = sqcl[b * 3 + 2];
            dice_acc += (2.f * inter + 1e-5f) / (psum + gsum + 1e-5f);
        }
        const float cldice = 1.f - dice_acc / (float)BATCH;

        float var_acc = 0.f, m2_acc = 0.f;
#pragma unroll
        for (int b = 0; b < BATCH; b++) {
            const float mean = sqdp[b * 6 + 0] / (float)DPIX;
            const float var = sqdp[b * 6 + 1] / (float)DPIX - mean * mean;
            var_acc += var;
            m2_acc += mean * mean;
        }
        const float silog = 10.f * (var_acc / (float)BATCH) + 10.f * (m2_acc / (float)BATCH);

        const float gx = sqdp[0 * 6 + 2] + sqdp[1 * 6 + 2];
        const float gy = sqdp[0 * 6 + 3] + sqdp[1 * 6 + 3];
        const float grad_l1 = gx / (float)(BATCH * 511 * 512) + gy / (float)(BATCH * 512 * 511);

        const float mask_l1 = (sqdp[0 * 6 + 4] + sqdp[1 * 6 + 4]) /
                              (sqdp[0 * 6 + 5] + sqdp[1 * 6 + 5] + 1e-8f);

        const float dloss = silog + grad_l1 + mask_l1;

        int it = iter[0];
        if (it < 1) it = 1;
        const float gamma1 = 2.f * logf((float)it / 20000.f);

        out[0] = gamma1 * chamfer + 0.5f * cldice + 0.01f * dloss;
    }
}

extern "C" void kernel_launch(void* const* d_in, const int* in_sizes, int n_in,
                              void* d_out, int out_size) {
    const float* pc = (const float*)d_in[0];   // pred_centers [2,8192,3]
    const float* pv = (const float*)d_in[1];   // pred_volume  [2,1,64,128,128]
    const float* pd = (const float*)d_in[2];   // pred_depth   [2,512,512]
    const float* gp = (const float*)d_in[3];   // gt_points    [2,8192,3]
    const float* gv = (const float*)d_in[4];   // gt_volume    [2,1,64,128,128]
    const float* gd = (const float*)d_in[5];   // gt_depth     [2,512,512]
    const float* dm = (const float*)d_in[6];   // depth_mask   [2,512,512]
    const int* it   = (const int*)d_in[7];     // iteration (scalar)

    mega_kernel<<<TOT_BLKS, TPB>>>(pc, pv, pd, gp, gv, gd, dm, it, (float*)d_out);
}